// round 6
// baseline (speedup 1.0000x reference)
#include <cuda_runtime.h>

#define N_ITEMS 100000
#define N_EDGES 800000
#define DIM     64
#define NV4     (N_ITEMS * DIM / 4)      // 1.6M float4 per buffer
#define CAP     32                       // Poisson(8): P(deg>32) ~ 1e-11
#define CHUNK   8

__device__ int    g_cnt[N_ITEMS];
__device__ int2   g_bucket[(size_t)N_ITEMS * CAP];   // {col, val-bits}, row stride 256B
__device__ float4 g_y1[NV4];
__device__ float4 g_y2[NV4];

// ---------------- bucket build ----------------

__global__ void k_scatter(const int* __restrict__ rows,
                          const int* __restrict__ cols,
                          const float* __restrict__ vals) {
    int e = blockIdx.x * blockDim.x + threadIdx.x;
    if (e >= N_EDGES) return;
    int r = rows[e];
    int p = atomicAdd(&g_cnt[r], 1);
    if (p < CAP) {
        int2 ed;
        ed.x = cols[e];
        ed.y = __float_as_int(vals[e]);
        g_bucket[(size_t)r * CAP + p] = ed;
    }
}

// zero-pad each row's bucket from cnt up to the next multiple of CHUNK,
// so layer kernels can load whole chunks unconditionally.
__global__ void k_pad() {
    int t = blockIdx.x * blockDim.x + threadIdx.x;   // N_ITEMS * 8 threads
    int r = t >> 3;
    int j = t & 7;
    if (r >= N_ITEMS) return;
    int c = g_cnt[r];
    if (c > CAP) c = CAP;
    int pe = (c + CHUNK - 1) & ~(CHUNK - 1);         // padded end
    int slot = c + j;
    if (slot < pe && slot < CAP)
        g_bucket[(size_t)r * CAP + slot] = make_int2(0, 0);
}

// ---------------- row-owned gather layers ----------------
// MODE 1: y = spmm(emb)       MODE 2: y = spmm(y1)
// MODE 3: out = (emb + y1 + y2 + spmm(y2)) * 0.25

template <int MODE>
__global__ void __launch_bounds__(128)
k_layer(const float4* __restrict__ x,
        float4* __restrict__ y,
        float4* __restrict__ out,
        const float4* __restrict__ emb,
        const float4* __restrict__ y1,
        const float4* __restrict__ y2) {
    int t = blockIdx.x * blockDim.x + threadIdx.x;
    int r = t >> 4;
    int l = t & 15;
    if (r >= N_ITEMS) return;

    int n = g_cnt[r];
    n = (n < 0) ? 0 : ((n > CAP) ? CAP : n);
    const int4* ep4 = (const int4*)&g_bucket[(size_t)r * CAP];  // 2 edges / int4

    float4 acc = make_float4(0.f, 0.f, 0.f, 0.f);

    for (int base = 0; base < n; base += CHUNK) {
        // 1) unconditional vector loads of 8 edges (padded region guarantees validity;
        //    pad slots are c=0, v=+0.0f). Independent of the cnt load.
        int4 p0 = ep4[(base >> 1) + 0];
        int4 p1 = ep4[(base >> 1) + 1];
        int4 p2 = ep4[(base >> 1) + 2];
        int4 p3 = ep4[(base >> 1) + 3];

        int   cs[CHUNK] = { p0.x, p0.z, p1.x, p1.z, p2.x, p2.z, p3.x, p3.z };
        int   vs[CHUNK] = { p0.y, p0.w, p1.y, p1.w, p2.y, p2.w, p3.y, p3.w };

        // 2) batch gathers (clamped addresses: provably in range)
        float4 xs[CHUNK];
        #pragma unroll
        for (int k = 0; k < CHUNK; k++) {
            unsigned c = (unsigned)cs[k];
            c = (c < N_ITEMS) ? c : (N_ITEMS - 1);
            xs[k] = __ldg(&x[(size_t)c * 16 + l]);
        }

        // 3) accumulate
        #pragma unroll
        for (int k = 0; k < CHUNK; k++) {
            float v = __int_as_float(vs[k]);
            acc.x += v * xs[k].x;
            acc.y += v * xs[k].y;
            acc.z += v * xs[k].z;
            acc.w += v * xs[k].w;
        }
    }

    int idx = r * 16 + l;
    if (MODE == 3) {
        float4 a  = __ldcs(&emb[idx]);
        float4 a1 = __ldcs(&y1[idx]);
        float4 a2 = __ldcs(&y2[idx]);
        float4 o  = make_float4((a.x + a1.x + a2.x + acc.x) * 0.25f,
                                (a.y + a1.y + a2.y + acc.y) * 0.25f,
                                (a.z + a1.z + a2.z + acc.z) * 0.25f,
                                (a.w + a1.w + a2.w + acc.w) * 0.25f);
        __stcs(&out[idx], o);
    } else {
        y[idx] = acc;
    }
}

extern "C" void kernel_launch(void* const* d_in, const int* in_sizes, int n_in,
                              void* d_out, int out_size) {
    const int*    rows = (const int*)d_in[0];
    const int*    cols = (const int*)d_in[1];
    const float*  vals = (const float*)d_in[2];
    const float4* emb  = (const float4*)d_in[3];
    float4* out = (float4*)d_out;

    int* cnt;   cudaGetSymbolAddress((void**)&cnt, g_cnt);
    float4* y1; cudaGetSymbolAddress((void**)&y1, g_y1);
    float4* y2; cudaGetSymbolAddress((void**)&y2, g_y2);

    const int edge_blocks  = (N_EDGES + 255) / 256;            // 3125
    const int pad_blocks   = (N_ITEMS * 8 + 255) / 256;        // 3125
    const int layer_blocks = (N_ITEMS * 16 + 127) / 128;       // 12500

    cudaMemsetAsync(cnt, 0, N_ITEMS * sizeof(int));
    k_scatter<<<edge_blocks, 256>>>(rows, cols, vals);
    k_pad    <<<pad_blocks, 256>>>();

    k_layer<1><<<layer_blocks, 128>>>(emb, y1, (float4*)nullptr, emb, y1, y2);
    k_layer<2><<<layer_blocks, 128>>>(y1, y2, (float4*)nullptr, emb, y1, y2);
    k_layer<3><<<layer_blocks, 128>>>(y2, (float4*)nullptr, out, emb, y1, y2);
}